// round 2
// baseline (speedup 1.0000x reference)
#include <cuda_runtime.h>
#include <math_constants.h>

#define Bq 4
#define Hh 12
#define Ss 2048
#define Dd 64
#define BM 128
#define BN 64

__global__ __launch_bounds__(128, 3)
void sdp_flash_fp32(const float* __restrict__ Q, const float* __restrict__ K,
                    const float* __restrict__ V, float* __restrict__ O) {
    __shared__ float Ks[BN][Dd];
    __shared__ float Vs[BN][Dd];

    const int qtile = blockIdx.x;
    const int bh    = blockIdx.y;          // b*H + h
    const int b     = bh / Hh;
    const int h     = bh % Hh;
    const int tid   = threadIdx.x;

    const float scale = 0.03608439182435161f;   // 1/sqrt(768)

    const int m_row = qtile * BM + tid;
    const float* qptr = Q + ((size_t)bh * Ss + m_row) * Dd;

    float q[Dd];
    #pragma unroll
    for (int d = 0; d < Dd; d += 4) {
        float4 v4 = *(const float4*)(qptr + d);
        q[d]   = v4.x * scale;
        q[d+1] = v4.y * scale;
        q[d+2] = v4.z * scale;
        q[d+3] = v4.w * scale;
    }

    float acc[Dd];
    #pragma unroll
    for (int d = 0; d < Dd; d++) acc[d] = 0.f;
    float m_run = -CUDART_INF_F;
    float l_run = 0.f;

    const float* kbase = K + (size_t)bh * Ss * Dd;
    const float* vbase = V + ((size_t)b * Ss * Hh + h) * Dd;   // + k*H*D per row

    for (int kt = 0; kt < Ss; kt += BN) {
        // --- stage K tile (coalesced, contiguous rows) ---
        const float4* ksrc = (const float4*)(kbase + (size_t)kt * Dd);
        #pragma unroll
        for (int i = 0; i < (BN * Dd / 4) / 128; i++) {
            int idx = tid + i * 128;
            ((float4*)&Ks[0][0])[idx] = ksrc[idx];
        }
        // --- stage V tile (rows strided by H*D in gmem) ---
        #pragma unroll
        for (int i = 0; i < (BN * Dd / 4) / 128; i++) {
            int idx = tid + i * 128;
            int row = idx >> 4;      // idx / (D/4)
            int col = idx & 15;
            ((float4*)&Vs[0][0])[idx] =
                *(const float4*)(vbase + (size_t)(kt + row) * (Hh * Dd) + col * 4);
        }
        __syncthreads();

        for (int k = 0; k < BN; k++) {
            // ---- score: dot(q, K[k]) with 4 independent accumulator chains ----
            float s0 = 0.f, s1 = 0.f, s2 = 0.f, s3 = 0.f;
            #pragma unroll
            for (int d = 0; d < Dd; d += 4) {
                float4 kv = *(const float4*)&Ks[k][d];   // broadcast LDS.128
                s0 += q[d]   * kv.x;
                s1 += q[d+1] * kv.y;
                s2 += q[d+2] * kv.z;
                s3 += q[d+3] * kv.w;
            }
            float s = (s0 + s1) + (s2 + s3);

            // ---- online softmax, rescale only on new max ----
            if (s > m_run) {
                float c = __expf(m_run - s);   // 0 on first hit (m_run = -inf)
                l_run *= c;
                #pragma unroll
                for (int d = 0; d < Dd; d++) acc[d] *= c;
                m_run = s;
            }
            float p = __expf(s - m_run);
            l_run += p;

            // ---- PV accumulate ----
            #pragma unroll
            for (int d = 0; d < Dd; d += 4) {
                float4 vv = *(const float4*)&Vs[k][d];   // broadcast LDS.128
                acc[d]   += p * vv.x;
                acc[d+1] += p * vv.y;
                acc[d+2] += p * vv.z;
                acc[d+3] += p * vv.w;
            }
        }
        __syncthreads();
    }

    const float inv_l = 1.0f / l_run;
    float* optr = O + ((size_t)bh * Ss + m_row) * Dd;
    #pragma unroll
    for (int d = 0; d < Dd; d += 4) {
        float4 o4;
        o4.x = acc[d]   * inv_l;
        o4.y = acc[d+1] * inv_l;
        o4.z = acc[d+2] * inv_l;
        o4.w = acc[d+3] * inv_l;
        *(float4*)(optr + d) = o4;
    }
}

extern "C" void kernel_launch(void* const* d_in, const int* in_sizes, int n_in,
                              void* d_out, int out_size) {
    const float* Q = (const float*)d_in[0];
    const float* K = (const float*)d_in[1];
    const float* V = (const float*)d_in[2];
    float* O = (float*)d_out;

    dim3 grid(Ss / BM, Bq * Hh);   // (16, 48) = 768 CTAs
    dim3 block(128);
    sdp_flash_fp32<<<grid, block>>>(Q, K, V, O);
}

// round 4
// speedup vs baseline: 4.1720x; 4.1720x over previous
#include <cuda_runtime.h>
#include <math_constants.h>
#include <cstdint>

#define Bq 4
#define Hh 12
#define Ss 2048
#define Dd 64
#define BM 128
#define BN 32
#define NTI (Ss / BN)          // 64 kv tiles

// smem word-strides chosen for conflict-free mma fragment loads
#define QS_ST 68
#define KS_ST 68
#define VS_ST 72
#define PT_ST 18

// smem layout (float words)
#define QS_OFF 0
#define KS_OFF (BM * QS_ST)                 // 8704
#define KBUF   (BN * KS_ST)                 // 2176
#define VS_OFF (KS_OFF + 2 * KBUF)          // 13056
#define VBUF   (BN * VS_ST)                 // 2304
#define PT_OFF (VS_OFF + 2 * VBUF)          // 17664
#define PTW    (BN * PT_ST)                 // 576
#define SMEM_WORDS (PT_OFF + 8 * PTW)       // 22272 words = 89088 bytes

static __device__ __forceinline__ void mma8(float* c, const uint32_t* a, const uint32_t* b) {
    asm volatile(
        "mma.sync.aligned.m16n8k8.row.col.f32.tf32.tf32.f32 "
        "{%0,%1,%2,%3}, {%4,%5,%6,%7}, {%8,%9}, {%0,%1,%2,%3};"
        : "+f"(c[0]), "+f"(c[1]), "+f"(c[2]), "+f"(c[3])
        : "r"(a[0]), "r"(a[1]), "r"(a[2]), "r"(a[3]), "r"(b[0]), "r"(b[1]));
}
static __device__ __forceinline__ void cpa16(uint32_t dst, const void* src) {
    asm volatile("cp.async.cg.shared.global [%0], [%1], 16;" :: "r"(dst), "l"(src));
}
static __device__ __forceinline__ uint32_t fb(float x) { return __float_as_uint(x); }

__global__ __launch_bounds__(256, 2)
void fa_tf32(const float* __restrict__ Q, const float* __restrict__ K,
             const float* __restrict__ V, float* __restrict__ O) {
    extern __shared__ float sm[];
    const int tid  = threadIdx.x;
    const int warp = tid >> 5;
    const int lane = tid & 31;
    const int g    = lane >> 2;       // group id (rows of fragments)
    const int tg   = lane & 3;        // thread-in-group (cols of fragments)

    const int qtile = blockIdx.x;
    const int bh    = blockIdx.y;
    const int b     = bh / Hh;
    const int h     = bh % Hh;
    const float scale = 0.03608439182435161f;   // 1/sqrt(768)

    const float* Qg = Q + ((size_t)bh * Ss + (size_t)qtile * BM) * Dd;
    const float* Kg = K + (size_t)bh * Ss * Dd;
    const float* Vg = V + (size_t)b * Ss * Hh * Dd + (size_t)h * Dd;

    const uint32_t smb = (uint32_t)__cvta_generic_to_shared(sm);

    // ---- stage Q (scaled), natural layout, stride 68 ----
    #pragma unroll
    for (int i = 0; i < 8; i++) {
        int idx = tid + i * 256;            // 0..2047 float4s
        int row = idx >> 4, d4 = idx & 15;
        float4 v = ((const float4*)Qg)[idx];
        v.x *= scale; v.y *= scale; v.z *= scale; v.w *= scale;
        *(float4*)(sm + QS_OFF + row * QS_ST + d4 * 4) = v;
    }

    // ---- cp.async prologue: tiles 0 and 1 ----
    #pragma unroll
    for (int t = 0; t < 2; t++) {
        #pragma unroll
        for (int i = 0; i < 2; i++) {
            int idx = tid + i * 256;        // 0..511 float4s
            int key = idx >> 4, d4 = idx & 15;
            cpa16(smb + (KS_OFF + t * KBUF + key * KS_ST + d4 * 4) * 4,
                  Kg + (size_t)(t * BN + key) * Dd + d4 * 4);
            cpa16(smb + (VS_OFF + t * VBUF + key * VS_ST + d4 * 4) * 4,
                  Vg + (size_t)(t * BN + key) * (Hh * Dd) + d4 * 4);
        }
        asm volatile("cp.async.commit_group;");
    }
    __syncthreads();   // Q staging visible

    // ---- Q fragments (B operand of S^T mma), register-resident for whole kernel ----
    uint32_t qb[8][2][2];
    #pragma unroll
    for (int kk = 0; kk < 8; kk++)
        #pragma unroll
        for (int nt = 0; nt < 2; nt++) {
            const float* p = sm + QS_OFF + (warp * 16 + nt * 8 + g) * QS_ST + kk * 8 + tg;
            qb[kk][nt][0] = fb(p[0]);
            qb[kk][nt][1] = fb(p[4]);
        }

    float ot[4][2][4];                      // O^T accum: d-tiles x q-tiles x frag
    #pragma unroll
    for (int a = 0; a < 4; a++)
        #pragma unroll
        for (int c = 0; c < 2; c++)
            #pragma unroll
            for (int r = 0; r < 4; r++) ot[a][c][r] = 0.f;
    float mrun[4] = {-CUDART_INF_F, -CUDART_INF_F, -CUDART_INF_F, -CUDART_INF_F};
    float lrun[4] = {0.f, 0.f, 0.f, 0.f};

    float* PT = sm + PT_OFF + warp * PTW;   // per-warp P^T buffer

    #pragma unroll 1
    for (int kt = 0; kt < NTI; kt++) {
        const int buf = kt & 1;
        asm volatile("cp.async.wait_group 1;");
        __syncthreads();

        const float* Ks = sm + KS_OFF + buf * KBUF;
        const float* Vs = sm + VS_OFF + buf * VBUF;

        // ---- S^T = K * Q^T : m = keys(32), n = queries(16), k = d(64) ----
        float st[2][2][4];
        #pragma unroll
        for (int mt = 0; mt < 2; mt++)
            #pragma unroll
            for (int nt = 0; nt < 2; nt++)
                #pragma unroll
                for (int r = 0; r < 4; r++) st[mt][nt][r] = 0.f;

        #pragma unroll
        for (int mt = 0; mt < 2; mt++)
            #pragma unroll
            for (int kk = 0; kk < 8; kk++) {
                const float* p = Ks + (mt * 16 + g) * KS_ST + kk * 8 + tg;
                uint32_t a[4];
                a[0] = fb(p[0]);
                a[1] = fb(p[8 * KS_ST]);
                a[2] = fb(p[4]);
                a[3] = fb(p[8 * KS_ST + 4]);
                mma8(st[mt][0], a, qb[kk][0]);
                mma8(st[mt][1], a, qb[kk][1]);
            }

        // ---- online softmax over keys (column reduction via shfl over g-lanes) ----
        #pragma unroll
        for (int nt = 0; nt < 2; nt++)
            #pragma unroll
            for (int par = 0; par < 2; par++) {
                const int ci = nt * 2 + par;
                float mx = fmaxf(fmaxf(st[0][nt][par], st[0][nt][par + 2]),
                                 fmaxf(st[1][nt][par], st[1][nt][par + 2]));
                mx = fmaxf(mx, __shfl_xor_sync(0xFFFFFFFFu, mx, 4));
                mx = fmaxf(mx, __shfl_xor_sync(0xFFFFFFFFu, mx, 8));
                mx = fmaxf(mx, __shfl_xor_sync(0xFFFFFFFFu, mx, 16));
                const float mnew = fmaxf(mrun[ci], mx);
                const float cf = __expf(mrun[ci] - mnew);
                mrun[ci] = mnew;

                float s = 0.f;
                #pragma unroll
                for (int mt = 0; mt < 2; mt++) {
                    float p0 = __expf(st[mt][nt][par] - mnew);
                    float p1 = __expf(st[mt][nt][par + 2] - mnew);
                    st[mt][nt][par] = p0;
                    st[mt][nt][par + 2] = p1;
                    s += p0 + p1;
                }
                s += __shfl_xor_sync(0xFFFFFFFFu, s, 4);
                s += __shfl_xor_sync(0xFFFFFFFFu, s, 8);
                s += __shfl_xor_sync(0xFFFFFFFFu, s, 16);
                lrun[ci] = lrun[ci] * cf + s;

                #pragma unroll
                for (int mtd = 0; mtd < 4; mtd++) {
                    ot[mtd][nt][par]     *= cf;
                    ot[mtd][nt][par + 2] *= cf;
                }
            }

        // ---- store P^T to per-warp smem (accum layout -> A-feed layout) ----
        #pragma unroll
        for (int mt = 0; mt < 2; mt++)
            #pragma unroll
            for (int nt = 0; nt < 2; nt++) {
                *(float2*)(PT + (mt * 16 + g) * PT_ST + nt * 8 + 2 * tg) =
                    make_float2(st[mt][nt][0], st[mt][nt][1]);
                *(float2*)(PT + (mt * 16 + g + 8) * PT_ST + nt * 8 + 2 * tg) =
                    make_float2(st[mt][nt][2], st[mt][nt][3]);
            }
        __syncwarp();

        // ---- O^T += V^T * P^T : m = d(64), n = queries(16), k = keys(32) ----
        #pragma unroll
        for (int kk = 0; kk < 4; kk++) {
            uint32_t bb[2][2];
            #pragma unroll
            for (int nt = 0; nt < 2; nt++) {
                bb[nt][0] = fb(PT[(kk * 8 + tg) * PT_ST + nt * 8 + g]);
                bb[nt][1] = fb(PT[(kk * 8 + tg + 4) * PT_ST + nt * 8 + g]);
            }
            #pragma unroll
            for (int mtd = 0; mtd < 4; mtd++) {
                const float* p = Vs + (kk * 8 + tg) * VS_ST + mtd * 16 + g;
                uint32_t a[4];
                a[0] = fb(p[0]);
                a[1] = fb(p[8]);
                a[2] = fb(p[4 * VS_ST]);
                a[3] = fb(p[4 * VS_ST + 8]);
                mma8(ot[mtd][0], a, bb[0]);
                mma8(ot[mtd][1], a, bb[1]);
            }
        }

        __syncthreads();   // done reading buf before refill
        if (kt + 2 < NTI) {
            #pragma unroll
            for (int i = 0; i < 2; i++) {
                int idx = tid + i * 256;
                int key = idx >> 4, d4 = idx & 15;
                cpa16(smb + (KS_OFF + buf * KBUF + key * KS_ST + d4 * 4) * 4,
                      Kg + (size_t)((kt + 2) * BN + key) * Dd + d4 * 4);
                cpa16(smb + (VS_OFF + buf * VBUF + key * VS_ST + d4 * 4) * 4,
                      Vg + (size_t)((kt + 2) * BN + key) * (Hh * Dd) + d4 * 4);
            }
        }
        asm volatile("cp.async.commit_group;");
    }

    // ---- epilogue: normalize and write O[q][d] ----
    float inv[4];
    #pragma unroll
    for (int ci = 0; ci < 4; ci++) inv[ci] = 1.0f / lrun[ci];

    float* Og = O + ((size_t)bh * Ss + (size_t)qtile * BM + warp * 16) * Dd;
    #pragma unroll
    for (int mtd = 0; mtd < 4; mtd++)
        #pragma unroll
        for (int nt = 0; nt < 2; nt++)
            #pragma unroll
            for (int par = 0; par < 2; par++) {
                const int ci = nt * 2 + par;
                const int q = nt * 8 + 2 * tg + par;
                const int d = mtd * 16 + g;
                Og[q * Dd + d]     = ot[mtd][nt][par]     * inv[ci];
                Og[q * Dd + d + 8] = ot[mtd][nt][par + 2] * inv[ci];
            }
}

extern "C" void kernel_launch(void* const* d_in, const int* in_sizes, int n_in,
                              void* d_out, int out_size) {
    const float* Q = (const float*)d_in[0];
    const float* K = (const float*)d_in[1];
    const float* V = (const float*)d_in[2];
    float* O = (float*)d_out;

    cudaFuncSetAttribute(fa_tf32, cudaFuncAttributeMaxDynamicSharedMemorySize,
                         SMEM_WORDS * 4);

    dim3 grid(Ss / BM, Bq * Hh);   // (16, 48)
    dim3 block(256);
    fa_tf32<<<grid, block, SMEM_WORDS * 4>>>(Q, K, V, O);
}